// round 2
// baseline (speedup 1.0000x reference)
#include <cuda_runtime.h>
#include <math.h>

#define F_IN 128
#define C3   192   // 3 * OUT, fused z|r|h feature block
#define OUT  64
#define NMAX 50048
#define EMAX 800000

// Scratch (no allocations allowed in kernel_launch)
__device__ float  g_dinv[NMAX];
__device__ float  g_xw [(size_t)NMAX * C3];
__device__ float  g_agg[(size_t)NMAX * C3];
__device__ int    g_cnt[NMAX];
__device__ int    g_rowptr[NMAX + 1];
__device__ int    g_cursor[NMAX];
__device__ float2 g_csr[EMAX];     // {coef, __int_as_float(src)} sorted by dst

// ---------------------------------------------------------------- degree/norm + in-degree hist
__global__ void k_deg_init(int n) {
    int i = blockIdx.x * blockDim.x + threadIdx.x;
    if (i < n) { g_dinv[i] = 1.0f; g_cnt[i] = 0; }   // self-loop weight 1
}

__global__ void k_deg_edges(const int* __restrict__ dst,
                            const float* __restrict__ w, int e) {
    int i = blockIdx.x * blockDim.x + threadIdx.x;
    if (i < e) {
        int d = dst[i];
        atomicAdd(&g_dinv[d], w[i]);
        atomicAdd(&g_cnt[d], 1);
    }
}

__global__ void k_rsqrt(int n) {
    int i = blockIdx.x * blockDim.x + threadIdx.x;
    if (i < n) {
        float d = g_dinv[i];
        g_dinv[i] = (d > 0.0f) ? rsqrtf(d) : 0.0f;
    }
}

// ---------------------------------------------------------------- exclusive scan of g_cnt (single block)
__global__ void k_scan(int n) {
    __shared__ int ssum[1024];
    const int tid = threadIdx.x;
    const int chunk = (n + 1023) / 1024;
    const int start = tid * chunk;
    const int end   = min(start + chunk, n);

    int s = 0;
    for (int i = start; i < end; i++) s += g_cnt[i];
    ssum[tid] = s;
    __syncthreads();

    // inclusive Hillis-Steele scan over thread sums
    for (int d = 1; d < 1024; d <<= 1) {
        int t = (tid >= d) ? ssum[tid - d] : 0;
        __syncthreads();
        ssum[tid] += t;
        __syncthreads();
    }

    int off = ssum[tid] - s;   // exclusive prefix for this chunk
    for (int i = start; i < end; i++) {
        int c = g_cnt[i];
        g_rowptr[i] = off;
        g_cursor[i] = off;
        off += c;
    }
    if (tid == 1023) g_rowptr[n] = ssum[1023];
}

// ---------------------------------------------------------------- bin edges by dst, precompute coefficient
__global__ void k_fill(const int* __restrict__ src, const int* __restrict__ dst,
                       const float* __restrict__ w, int e) {
    int i = blockIdx.x * blockDim.x + threadIdx.x;
    if (i < e) {
        int s = src[i], d = dst[i];
        float cf = g_dinv[s] * w[i] * g_dinv[d];
        int p = atomicAdd(&g_cursor[d], 1);
        g_csr[p] = make_float2(cf, __int_as_float(s));
    }
}

// ---------------------------------------------------------------- XW = x @ [Wz|Wr|Wh]
__global__ void k_xw(const float* __restrict__ x,
                     const float* __restrict__ Wz,
                     const float* __restrict__ Wr,
                     const float* __restrict__ Wh, int n) {
    __shared__ float xs[64 * 32];    // [r][kk]
    __shared__ float ws[32 * 192];   // [kk][j]
    const int tid = threadIdx.x;
    const int row0 = blockIdx.x * 64;
    const int tx = tid & 15, ty = tid >> 4;

    float acc[4][12];
#pragma unroll
    for (int r = 0; r < 4; r++)
#pragma unroll
        for (int c = 0; c < 12; c++) acc[r][c] = 0.0f;

    for (int k0 = 0; k0 < F_IN; k0 += 32) {
        for (int i = tid; i < 2048; i += 256) {
            int r = i >> 5, kk = i & 31;
            int row = row0 + r;
            xs[r * 32 + kk] = (row < n) ? x[(size_t)row * F_IN + k0 + kk] : 0.0f;
        }
        for (int i = tid; i < 6144; i += 256) {
            int kk = i / 192, j = i - kk * 192;
            const float* W = (j < 64) ? Wz : ((j < 128) ? Wr : Wh);
            int jj = j & 63;
            ws[kk * 192 + j] = W[(k0 + kk) * 64 + jj];
        }
        __syncthreads();

#pragma unroll 8
        for (int kk = 0; kk < 32; kk++) {
            float b[12];
            *(float4*)&b[0] = *(const float4*)&ws[kk * 192 + tx * 12];
            *(float4*)&b[4] = *(const float4*)&ws[kk * 192 + tx * 12 + 4];
            *(float4*)&b[8] = *(const float4*)&ws[kk * 192 + tx * 12 + 8];
#pragma unroll
            for (int r = 0; r < 4; r++) {
                float a = xs[(ty * 4 + r) * 32 + kk];
#pragma unroll
                for (int c = 0; c < 12; c++) acc[r][c] += a * b[c];
            }
        }
        __syncthreads();
    }

#pragma unroll
    for (int r = 0; r < 4; r++) {
        int row = row0 + ty * 4 + r;
        if (row < n) {
            float* dp = &g_xw[(size_t)row * C3 + tx * 12];
#pragma unroll
            for (int c = 0; c < 12; c++) dp[c] = acc[r][c];
        }
    }
}

// ---------------------------------------------------------------- CSR gather aggregation (no atomics)
// One warp per destination node; 6 accumulators per lane; 2-edge unroll.
__global__ void k_gather(int n) {
    int warp = (blockIdx.x * blockDim.x + threadIdx.x) >> 5;
    if (warp >= n) return;
    const int lane = threadIdx.x & 31;

    const int r0 = g_rowptr[warp];
    const int r1 = g_rowptr[warp + 1];

    const float di = g_dinv[warp];
    const float sl = di * di;
    const float* __restrict__ xr = &g_xw[(size_t)warp * C3];

    float acc[6];
#pragma unroll
    for (int t = 0; t < 6; t++) acc[t] = sl * xr[lane + 32 * t];

    int p = r0;
    for (; p + 1 < r1; p += 2) {
        float2 e0 = g_csr[p];
        float2 e1 = g_csr[p + 1];
        const float* __restrict__ x0 = &g_xw[(size_t)__float_as_int(e0.y) * C3];
        const float* __restrict__ x1 = &g_xw[(size_t)__float_as_int(e1.y) * C3];
#pragma unroll
        for (int t = 0; t < 6; t++) {
            acc[t] += e0.x * x0[lane + 32 * t];
            acc[t] += e1.x * x1[lane + 32 * t];
        }
    }
    if (p < r1) {
        float2 e0 = g_csr[p];
        const float* __restrict__ x0 = &g_xw[(size_t)__float_as_int(e0.y) * C3];
#pragma unroll
        for (int t = 0; t < 6; t++) acc[t] += e0.x * x0[lane + 32 * t];
    }

    float* __restrict__ ar = &g_agg[(size_t)warp * C3];
#pragma unroll
    for (int t = 0; t < 6; t++) ar[lane + 32 * t] = acc[t];
}

// ---------------------------------------------------------------- fused gates + GRU + output
__global__ void k_gates(const float* __restrict__ H,
                        const float* __restrict__ bz, const float* __restrict__ br,
                        const float* __restrict__ bh,
                        const float* __restrict__ Lz, const float* __restrict__ lbz,
                        const float* __restrict__ Lr, const float* __restrict__ lbr,
                        const float* __restrict__ Lh, const float* __restrict__ lbh,
                        const float* __restrict__ Wo, const float* __restrict__ bo,
                        float* __restrict__ out, int n) {
    extern __shared__ float sm[];
    float* sLz = sm;                 // 128*64
    float* sLr = sm + 8192;          // 128*64
    float* sLh = sm + 16384;         // 128*64
    float* sA  = sm + 24576;         // 64*192
    float* sH  = sA + 12288;         // 64*64
    float* sR  = sH + 4096;          // 64*64 (H*R)

    const int tid = threadIdx.x;
    const int node0 = blockIdx.x * 64;

    for (int i = tid; i < 8192; i += 256) {
        sLz[i] = Lz[i]; sLr[i] = Lr[i]; sLh[i] = Lh[i];
    }
    for (int i = tid; i < 12288; i += 256) {
        int r = i / 192, j = i - r * 192;
        int node = node0 + r;
        float b = (j < 64) ? bz[j] : ((j < 128) ? br[j - 64] : bh[j - 128]);
        sA[i] = (node < n) ? g_agg[(size_t)node * C3 + j] + b : 0.0f;
    }
    for (int i = tid; i < 4096; i += 256) {
        int r = i >> 6;
        int node = node0 + r;
        sH[i] = (node < n) ? H[(size_t)node * OUT + (i & 63)] : 0.0f;
    }
    __syncthreads();

    const int tx = tid & 15, ty = tid >> 4;
    const int r0 = ty * 4, c0 = tx * 4;

    float zacc[4][4], racc[4][4];
#pragma unroll
    for (int cc = 0; cc < 4; cc++) {
        float vz = lbz[c0 + cc], vr = lbr[c0 + cc];
#pragma unroll
        for (int rr = 0; rr < 4; rr++) { zacc[rr][cc] = vz; racc[rr][cc] = vr; }
    }

#pragma unroll 4
    for (int k = 0; k < 64; k++) {
        float lz1[4], lz2[4], lr1[4], lr2[4];
        *(float4*)lz1 = *(const float4*)&sLz[k * 64 + c0];
        *(float4*)lz2 = *(const float4*)&sLz[(64 + k) * 64 + c0];
        *(float4*)lr1 = *(const float4*)&sLr[k * 64 + c0];
        *(float4*)lr2 = *(const float4*)&sLr[(64 + k) * 64 + c0];
#pragma unroll
        for (int rr = 0; rr < 4; rr++) {
            float az = sA[(r0 + rr) * 192 + k];
            float ag = sA[(r0 + rr) * 192 + 64 + k];
            float h  = sH[(r0 + rr) * 64 + k];
#pragma unroll
            for (int cc = 0; cc < 4; cc++) {
                zacc[rr][cc] += az * lz1[cc] + h * lz2[cc];
                racc[rr][cc] += ag * lr1[cc] + h * lr2[cc];
            }
        }
    }

#pragma unroll
    for (int rr = 0; rr < 4; rr++)
#pragma unroll
        for (int cc = 0; cc < 4; cc++) {
            zacc[rr][cc] = 1.0f / (1.0f + expf(-zacc[rr][cc]));
            float r_ = 1.0f / (1.0f + expf(-racc[rr][cc]));
            int idx = (r0 + rr) * 64 + c0 + cc;
            sR[idx] = r_ * sH[idx];
        }
    __syncthreads();

    float hacc[4][4];
#pragma unroll
    for (int cc = 0; cc < 4; cc++) {
        float vh = lbh[c0 + cc];
#pragma unroll
        for (int rr = 0; rr < 4; rr++) hacc[rr][cc] = vh;
    }

#pragma unroll 4
    for (int k = 0; k < 64; k++) {
        float lh1[4], lh2[4];
        *(float4*)lh1 = *(const float4*)&sLh[k * 64 + c0];
        *(float4*)lh2 = *(const float4*)&sLh[(64 + k) * 64 + c0];
#pragma unroll
        for (int rr = 0; rr < 4; rr++) {
            float ah = sA[(r0 + rr) * 192 + 128 + k];
            float hr = sR[(r0 + rr) * 64 + k];
#pragma unroll
            for (int cc = 0; cc < 4; cc++)
                hacc[rr][cc] += ah * lh1[cc] + hr * lh2[cc];
        }
    }

    float wov[4];
#pragma unroll
    for (int cc = 0; cc < 4; cc++) wov[cc] = Wo[c0 + cc];
    float yp[4] = {0.f, 0.f, 0.f, 0.f};

#pragma unroll
    for (int rr = 0; rr < 4; rr++) {
        int node = node0 + r0 + rr;
#pragma unroll
        for (int cc = 0; cc < 4; cc++) {
            float ht = tanhf(hacc[rr][cc]);
            float z = zacc[rr][cc];
            float h = sH[(r0 + rr) * 64 + c0 + cc];
            float hn = z * h + (1.0f - z) * ht;
            if (node < n) out[(size_t)n + (size_t)node * OUT + c0 + cc] = hn;
            yp[rr] += fmaxf(hn, 0.0f) * wov[cc];
        }
    }
#pragma unroll
    for (int off = 8; off > 0; off >>= 1)
#pragma unroll
        for (int rr = 0; rr < 4; rr++)
            yp[rr] += __shfl_xor_sync(0xffffffffu, yp[rr], off);
    if (tx == 0) {
        float b0 = bo[0];
#pragma unroll
        for (int rr = 0; rr < 4; rr++) {
            int node = node0 + r0 + rr;
            if (node < n) out[node] = yp[rr] + b0;
        }
    }
}

// ---------------------------------------------------------------- launch
extern "C" void kernel_launch(void* const* d_in, const int* in_sizes, int n_in,
                              void* d_out, int out_size) {
    const float* x   = (const float*)d_in[0];
    const int*   ei  = (const int*)d_in[1];
    const float* ew  = (const float*)d_in[2];
    const float* H   = (const float*)d_in[3];
    // d_in[4] = c (unused)
    const float* Wz  = (const float*)d_in[5];
    const float* bz  = (const float*)d_in[6];
    const float* Wr  = (const float*)d_in[7];
    const float* br  = (const float*)d_in[8];
    const float* Wh  = (const float*)d_in[9];
    const float* bh  = (const float*)d_in[10];
    const float* Lz  = (const float*)d_in[11];
    const float* lbz = (const float*)d_in[12];
    const float* Lr  = (const float*)d_in[13];
    const float* lbr = (const float*)d_in[14];
    const float* Lh  = (const float*)d_in[15];
    const float* lbh = (const float*)d_in[16];
    const float* Wo  = (const float*)d_in[17];
    const float* bo  = (const float*)d_in[18];
    float* out = (float*)d_out;

    int n = in_sizes[0] / F_IN;
    int e = in_sizes[2];
    const int* src = ei;
    const int* dst = ei + e;

    k_deg_init <<<(n + 255) / 256, 256>>>(n);
    k_deg_edges<<<(e + 255) / 256, 256>>>(dst, ew, e);
    k_rsqrt    <<<(n + 255) / 256, 256>>>(n);
    k_scan     <<<1, 1024>>>(n);
    k_fill     <<<(e + 255) / 256, 256>>>(src, dst, ew, e);
    k_xw       <<<(n + 63) / 64, 256>>>(x, Wz, Wr, Wh, n);
    k_gather   <<<(n * 32 + 255) / 256, 256>>>(n);

    cudaFuncSetAttribute(k_gates, cudaFuncAttributeMaxDynamicSharedMemorySize, 180224);
    k_gates<<<(n + 63) / 64, 256, 180224>>>(H, bz, br, bh, Lz, lbz, Lr, lbr,
                                            Lh, lbh, Wo, bo, out, n);
}

// round 3
// speedup vs baseline: 1.4172x; 1.4172x over previous
#include <cuda_runtime.h>
#include <math.h>

#define F_IN 128
#define C3   192   // 3 * OUT
#define OUT  64
#define NMAX 50048
#define EMAX 800000

__device__ float  g_dinv[NMAX];
__device__ float  g_xw [(size_t)NMAX * C3];
__device__ float  g_agg[(size_t)NMAX * C3];
__device__ int    g_cnt[NMAX];
__device__ int    g_rowptr[NMAX + 1];
__device__ int    g_cursor[NMAX];
__device__ int    g_bsum[64];
__device__ int    g_boff[64];
__device__ float2 g_csr[EMAX];     // {coef, __int_as_float(src)} binned by dst

// ---------------------------------------------------------------- degree/norm + in-degree hist
__global__ void k_deg_init(int n) {
    int i = blockIdx.x * blockDim.x + threadIdx.x;
    if (i < n) { g_dinv[i] = 1.0f; g_cnt[i] = 0; }
}

__global__ void k_deg_edges(const int* __restrict__ dst,
                            const float* __restrict__ w, int e) {
    int i = blockIdx.x * blockDim.x + threadIdx.x;
    if (i < e) {
        int d = dst[i];
        atomicAdd(&g_dinv[d], w[i]);
        atomicAdd(&g_cnt[d], 1);
    }
}

__global__ void k_rsqrt(int n) {
    int i = blockIdx.x * blockDim.x + threadIdx.x;
    if (i < n) {
        float d = g_dinv[i];
        g_dinv[i] = (d > 0.0f) ? rsqrtf(d) : 0.0f;
    }
}

// ---------------------------------------------------------------- coalesced hierarchical scan
__global__ void k_scan_a(int n) {          // per-1024-block local exclusive scan
    __shared__ int s[1024];
    int tid = threadIdx.x;
    int i = blockIdx.x * 1024 + tid;
    int v = (i < n) ? g_cnt[i] : 0;
    s[tid] = v;
    __syncthreads();
    for (int d = 1; d < 1024; d <<= 1) {
        int t = (tid >= d) ? s[tid - d] : 0;
        __syncthreads();
        s[tid] += t;
        __syncthreads();
    }
    if (i < n) g_rowptr[i] = s[tid] - v;   // local exclusive
    if (tid == 1023) g_bsum[blockIdx.x] = s[1023];
}

__global__ void k_scan_b(int n, int nblk) {   // scan the <=64 block sums
    __shared__ int s[64];
    int tid = threadIdx.x;
    int v = (tid < nblk) ? g_bsum[tid] : 0;
    s[tid] = v;
    __syncthreads();
    for (int d = 1; d < 64; d <<= 1) {
        int t = (tid >= d) ? s[tid - d] : 0;
        __syncthreads();
        s[tid] += t;
        __syncthreads();
    }
    if (tid < nblk) g_boff[tid] = s[tid] - v;
    if (tid == 63) g_rowptr[n] = s[63];
}

__global__ void k_scan_c(int n) {          // add block offsets
    int i = blockIdx.x * blockDim.x + threadIdx.x;
    if (i < n) {
        int v = g_rowptr[i] + g_boff[i >> 10];
        g_rowptr[i] = v;
        g_cursor[i] = v;
    }
}

// ---------------------------------------------------------------- bin edges by dst
__global__ void k_fill(const int* __restrict__ src, const int* __restrict__ dst,
                       const float* __restrict__ w, int e) {
    int i = blockIdx.x * blockDim.x + threadIdx.x;
    if (i < e) {
        int s = src[i], d = dst[i];
        float cf = g_dinv[s] * w[i] * g_dinv[d];
        int p = atomicAdd(&g_cursor[d], 1);
        g_csr[p] = make_float2(cf, __int_as_float(s));
    }
}

// ---------------------------------------------------------------- XW = x @ [Wz|Wr|Wh]
__global__ void k_xw(const float* __restrict__ x,
                     const float* __restrict__ Wz,
                     const float* __restrict__ Wr,
                     const float* __restrict__ Wh, int n) {
    __shared__ float xs[64 * 32];
    __shared__ float ws[32 * 192];
    const int tid = threadIdx.x;
    const int row0 = blockIdx.x * 64;
    const int tx = tid & 15, ty = tid >> 4;

    float acc[4][12];
#pragma unroll
    for (int r = 0; r < 4; r++)
#pragma unroll
        for (int c = 0; c < 12; c++) acc[r][c] = 0.0f;

    for (int k0 = 0; k0 < F_IN; k0 += 32) {
        for (int i = tid; i < 2048; i += 256) {
            int r = i >> 5, kk = i & 31;
            int row = row0 + r;
            xs[r * 32 + kk] = (row < n) ? x[(size_t)row * F_IN + k0 + kk] : 0.0f;
        }
        for (int i = tid; i < 6144; i += 256) {
            int kk = i / 192, j = i - kk * 192;
            const float* W = (j < 64) ? Wz : ((j < 128) ? Wr : Wh);
            int jj = j & 63;
            ws[kk * 192 + j] = W[(k0 + kk) * 64 + jj];
        }
        __syncthreads();

#pragma unroll 8
        for (int kk = 0; kk < 32; kk++) {
            float b[12];
            *(float4*)&b[0] = *(const float4*)&ws[kk * 192 + tx * 12];
            *(float4*)&b[4] = *(const float4*)&ws[kk * 192 + tx * 12 + 4];
            *(float4*)&b[8] = *(const float4*)&ws[kk * 192 + tx * 12 + 8];
#pragma unroll
            for (int r = 0; r < 4; r++) {
                float a = xs[(ty * 4 + r) * 32 + kk];
#pragma unroll
                for (int c = 0; c < 12; c++) acc[r][c] += a * b[c];
            }
        }
        __syncthreads();
    }

#pragma unroll
    for (int r = 0; r < 4; r++) {
        int row = row0 + ty * 4 + r;
        if (row < n) {
            float* dp = &g_xw[(size_t)row * C3 + tx * 12];
#pragma unroll
            for (int c = 0; c < 12; c++) dp[c] = acc[r][c];
        }
    }
}

// ---------------------------------------------------------------- CSR gather (no atomics)
__global__ void k_gather(int n) {
    int warp = (blockIdx.x * blockDim.x + threadIdx.x) >> 5;
    if (warp >= n) return;
    const int lane = threadIdx.x & 31;

    const int r0 = g_rowptr[warp];
    const int r1 = g_rowptr[warp + 1];

    const float di = g_dinv[warp];
    const float sl = di * di;
    const float* __restrict__ xr = &g_xw[(size_t)warp * C3];

    float acc[6];
#pragma unroll
    for (int t = 0; t < 6; t++) acc[t] = sl * xr[lane + 32 * t];

    int p = r0;
    for (; p + 1 < r1; p += 2) {
        float2 e0 = g_csr[p];
        float2 e1 = g_csr[p + 1];
        const float* __restrict__ x0 = &g_xw[(size_t)__float_as_int(e0.y) * C3];
        const float* __restrict__ x1 = &g_xw[(size_t)__float_as_int(e1.y) * C3];
#pragma unroll
        for (int t = 0; t < 6; t++) {
            acc[t] += e0.x * x0[lane + 32 * t];
            acc[t] += e1.x * x1[lane + 32 * t];
        }
    }
    if (p < r1) {
        float2 e0 = g_csr[p];
        const float* __restrict__ x0 = &g_xw[(size_t)__float_as_int(e0.y) * C3];
#pragma unroll
        for (int t = 0; t < 6; t++) acc[t] += e0.x * x0[lane + 32 * t];
    }

    float* __restrict__ ar = &g_agg[(size_t)warp * C3];
#pragma unroll
    for (int t = 0; t < 6; t++) ar[lane + 32 * t] = acc[t];
}

// ---------------------------------------------------------------- fused gates + GRU + output
// 128-node tile, 512 threads, phased smem overlay (192KB):
//   phase1: sH | sHR | [Lz|Lr] | [aggz|aggr]   phase2: sH | sHR | [Lh|--] | [aggh|--]
__global__ __launch_bounds__(512, 1)
void k_gates(const float* __restrict__ H,
             const float* __restrict__ bz, const float* __restrict__ br,
             const float* __restrict__ bh,
             const float* __restrict__ Lz, const float* __restrict__ lbz,
             const float* __restrict__ Lr, const float* __restrict__ lbr,
             const float* __restrict__ Lh, const float* __restrict__ lbh,
             const float* __restrict__ Wo, const float* __restrict__ bo,
             float* __restrict__ out, int n) {
    extern __shared__ float sm[];
    float* sH  = sm;            // 128*64
    float* sHR = sm + 8192;     // 128*64
    float* sL  = sm + 16384;    // 2 * 128*64
    float* sA  = sm + 32768;    // 2 * 128*64

    const int tid = threadIdx.x;
    const int node0 = blockIdx.x * 128;

    for (int i = tid; i < 8192; i += 512) {
        int r = i >> 6;
        int node = node0 + r;
        sH[i] = (node < n) ? H[(size_t)node * OUT + (i & 63)] : 0.0f;
    }
    for (int i = tid; i < 8192; i += 512) {
        sL[i] = Lz[i];
        sL[8192 + i] = Lr[i];
    }
    for (int i = tid; i < 8192; i += 512) {
        int r = i >> 6, j = i & 63;
        int node = node0 + r;
        if (node < n) {
            const float* ag = &g_agg[(size_t)node * C3];
            sA[i]        = ag[j]      + bz[j];
            sA[8192 + i] = ag[64 + j] + br[j];
        } else {
            sA[i] = 0.0f; sA[8192 + i] = 0.0f;
        }
    }
    __syncthreads();

    const int tx = tid & 15, ty = tid >> 4;
    const int r0 = ty * 4, c0 = tx * 4;

    float zacc[4][4], racc[4][4];
#pragma unroll
    for (int cc = 0; cc < 4; cc++) {
        float vz = lbz[c0 + cc], vr = lbr[c0 + cc];
#pragma unroll
        for (int rr = 0; rr < 4; rr++) { zacc[rr][cc] = vz; racc[rr][cc] = vr; }
    }

#pragma unroll 4
    for (int k = 0; k < 64; k++) {
        float lz1[4], lz2[4], lr1[4], lr2[4];
        *(float4*)lz1 = *(const float4*)&sL[k * 64 + c0];
        *(float4*)lz2 = *(const float4*)&sL[(64 + k) * 64 + c0];
        *(float4*)lr1 = *(const float4*)&sL[8192 + k * 64 + c0];
        *(float4*)lr2 = *(const float4*)&sL[8192 + (64 + k) * 64 + c0];
#pragma unroll
        for (int rr = 0; rr < 4; rr++) {
            float az = sA[(r0 + rr) * 64 + k];
            float ar = sA[8192 + (r0 + rr) * 64 + k];
            float h  = sH[(r0 + rr) * 64 + k];
#pragma unroll
            for (int cc = 0; cc < 4; cc++) {
                zacc[rr][cc] += az * lz1[cc] + h * lz2[cc];
                racc[rr][cc] += ar * lr1[cc] + h * lr2[cc];
            }
        }
    }

#pragma unroll
    for (int rr = 0; rr < 4; rr++)
#pragma unroll
        for (int cc = 0; cc < 4; cc++) {
            zacc[rr][cc] = 1.0f / (1.0f + expf(-zacc[rr][cc]));
            float r_ = 1.0f / (1.0f + expf(-racc[rr][cc]));
            int idx = (r0 + rr) * 64 + c0 + cc;
            sHR[idx] = r_ * sH[idx];
        }
    __syncthreads();

    // phase 2 overlays
    for (int i = tid; i < 8192; i += 512) sL[i] = Lh[i];
    for (int i = tid; i < 8192; i += 512) {
        int r = i >> 6, j = i & 63;
        int node = node0 + r;
        sA[i] = (node < n) ? g_agg[(size_t)node * C3 + 128 + j] + bh[j] : 0.0f;
    }
    __syncthreads();

    float hacc[4][4];
#pragma unroll
    for (int cc = 0; cc < 4; cc++) {
        float vh = lbh[c0 + cc];
#pragma unroll
        for (int rr = 0; rr < 4; rr++) hacc[rr][cc] = vh;
    }

#pragma unroll 4
    for (int k = 0; k < 64; k++) {
        float lh1[4], lh2[4];
        *(float4*)lh1 = *(const float4*)&sL[k * 64 + c0];
        *(float4*)lh2 = *(const float4*)&sL[(64 + k) * 64 + c0];
#pragma unroll
        for (int rr = 0; rr < 4; rr++) {
            float ah = sA[(r0 + rr) * 64 + k];
            float hr = sHR[(r0 + rr) * 64 + k];
#pragma unroll
            for (int cc = 0; cc < 4; cc++)
                hacc[rr][cc] += ah * lh1[cc] + hr * lh2[cc];
        }
    }

    float wov[4];
#pragma unroll
    for (int cc = 0; cc < 4; cc++) wov[cc] = Wo[c0 + cc];
    float yp[4] = {0.f, 0.f, 0.f, 0.f};

#pragma unroll
    for (int rr = 0; rr < 4; rr++) {
        int node = node0 + r0 + rr;
#pragma unroll
        for (int cc = 0; cc < 4; cc++) {
            float ht = tanhf(hacc[rr][cc]);
            float z = zacc[rr][cc];
            float h = sH[(r0 + rr) * 64 + c0 + cc];
            float hn = z * h + (1.0f - z) * ht;
            if (node < n) out[(size_t)n + (size_t)node * OUT + c0 + cc] = hn;
            yp[rr] += fmaxf(hn, 0.0f) * wov[cc];
        }
    }
    // reduce across the 16 tx lanes (xor offsets stay within 16-lane half-warp)
#pragma unroll
    for (int off = 8; off > 0; off >>= 1)
#pragma unroll
        for (int rr = 0; rr < 4; rr++)
            yp[rr] += __shfl_xor_sync(0xffffffffu, yp[rr], off);
    if (tx == 0) {
        float b0 = bo[0];
#pragma unroll
        for (int rr = 0; rr < 4; rr++) {
            int node = node0 + r0 + rr;
            if (node < n) out[node] = yp[rr] + b0;
        }
    }
}

// ---------------------------------------------------------------- launch
extern "C" void kernel_launch(void* const* d_in, const int* in_sizes, int n_in,
                              void* d_out, int out_size) {
    const float* x   = (const float*)d_in[0];
    const int*   ei  = (const int*)d_in[1];
    const float* ew  = (const float*)d_in[2];
    const float* H   = (const float*)d_in[3];
    const float* Wz  = (const float*)d_in[5];
    const float* bz  = (const float*)d_in[6];
    const float* Wr  = (const float*)d_in[7];
    const float* br  = (const float*)d_in[8];
    const float* Wh  = (const float*)d_in[9];
    const float* bh  = (const float*)d_in[10];
    const float* Lz  = (const float*)d_in[11];
    const float* lbz = (const float*)d_in[12];
    const float* Lr  = (const float*)d_in[13];
    const float* lbr = (const float*)d_in[14];
    const float* Lh  = (const float*)d_in[15];
    const float* lbh = (const float*)d_in[16];
    const float* Wo  = (const float*)d_in[17];
    const float* bo  = (const float*)d_in[18];
    float* out = (float*)d_out;

    int n = in_sizes[0] / F_IN;
    int e = in_sizes[2];
    const int* src = ei;
    const int* dst = ei + e;
    int nblk = (n + 1023) / 1024;

    k_deg_init <<<(n + 255) / 256, 256>>>(n);
    k_deg_edges<<<(e + 255) / 256, 256>>>(dst, ew, e);
    k_rsqrt    <<<(n + 255) / 256, 256>>>(n);
    k_scan_a   <<<nblk, 1024>>>(n);
    k_scan_b   <<<1, 64>>>(n, nblk);
    k_scan_c   <<<(n + 255) / 256, 256>>>(n);
    k_fill     <<<(e + 255) / 256, 256>>>(src, dst, ew, e);
    k_xw       <<<(n + 63) / 64, 256>>>(x, Wz, Wr, Wh, n);
    k_gather   <<<(n * 32 + 255) / 256, 256>>>(n);

    cudaFuncSetAttribute(k_gates, cudaFuncAttributeMaxDynamicSharedMemorySize, 196608);
    k_gates<<<(n + 127) / 128, 512, 196608>>>(H, bz, br, bh, Lz, lbz, Lr, lbr,
                                              Lh, lbh, Wo, bo, out, n);
}

// round 5
// speedup vs baseline: 1.5666x; 1.1054x over previous
#include <cuda_runtime.h>
#include <math.h>

#define F_IN 128
#define C3   192   // 3 * OUT
#define OUT  64
#define NMAX 50048
#define EMAX 800000

typedef unsigned long long u64;

// packed f32x2 FMA (Blackwell FFMA2 — only reachable via PTX)
#define FFMA2(d, a, b, c) \
    asm("fma.rn.f32x2 %0, %1, %2, %3;" : "=l"(d) : "l"(a), "l"(b), "l"(c))
#define PACK2(d, lo, hi) \
    asm("mov.b64 %0, {%1, %2};" : "=l"(d) : "f"(lo), "f"(hi))
#define UNPACK2(lo, hi, s) \
    asm("mov.b64 {%0, %1}, %2;" : "=f"(lo), "=f"(hi) : "l"(s))

__device__ float  g_dinv[NMAX];
__device__ float  g_xw [(size_t)NMAX * C3];
__device__ float  g_agg[(size_t)NMAX * C3];
__device__ int    g_cnt[NMAX];
__device__ int    g_rowptr[NMAX + 1];
__device__ int    g_cursor[NMAX];
__device__ int    g_bsum[64];
__device__ int    g_boff[64];
__device__ float2 g_csr[EMAX];     // {coef, __int_as_float(src)} binned by dst

// ---------------------------------------------------------------- degree/norm + in-degree hist
__global__ void k_deg_init(int n) {
    int i = blockIdx.x * blockDim.x + threadIdx.x;
    if (i < n) { g_dinv[i] = 1.0f; g_cnt[i] = 0; }
}

__global__ void k_deg_edges(const int* __restrict__ dst,
                            const float* __restrict__ w, int e) {
    int i = blockIdx.x * blockDim.x + threadIdx.x;
    if (i < e) {
        int d = dst[i];
        atomicAdd(&g_dinv[d], w[i]);
        atomicAdd(&g_cnt[d], 1);
    }
}

__global__ void k_rsqrt(int n) {
    int i = blockIdx.x * blockDim.x + threadIdx.x;
    if (i < n) {
        float d = g_dinv[i];
        g_dinv[i] = (d > 0.0f) ? rsqrtf(d) : 0.0f;
    }
}

// ---------------------------------------------------------------- coalesced hierarchical scan
__global__ void k_scan_a(int n) {
    __shared__ int s[1024];
    int tid = threadIdx.x;
    int i = blockIdx.x * 1024 + tid;
    int v = (i < n) ? g_cnt[i] : 0;
    s[tid] = v;
    __syncthreads();
    for (int d = 1; d < 1024; d <<= 1) {
        int t = (tid >= d) ? s[tid - d] : 0;
        __syncthreads();
        s[tid] += t;
        __syncthreads();
    }
    if (i < n) g_rowptr[i] = s[tid] - v;
    if (tid == 1023) g_bsum[blockIdx.x] = s[1023];
}

__global__ void k_scan_b(int n, int nblk) {
    __shared__ int s[64];
    int tid = threadIdx.x;
    int v = (tid < nblk) ? g_bsum[tid] : 0;
    s[tid] = v;
    __syncthreads();
    for (int d = 1; d < 64; d <<= 1) {
        int t = (tid >= d) ? s[tid - d] : 0;
        __syncthreads();
        s[tid] += t;
        __syncthreads();
    }
    if (tid < nblk) g_boff[tid] = s[tid] - v;
    if (tid == 63) g_rowptr[n] = s[63];
}

__global__ void k_scan_c(int n) {
    int i = blockIdx.x * blockDim.x + threadIdx.x;
    if (i < n) {
        int v = g_rowptr[i] + g_boff[i >> 10];
        g_rowptr[i] = v;
        g_cursor[i] = v;
    }
}

// ---------------------------------------------------------------- bin edges by dst
__global__ void k_fill(const int* __restrict__ src, const int* __restrict__ dst,
                       const float* __restrict__ w, int e) {
    int i = blockIdx.x * blockDim.x + threadIdx.x;
    if (i < e) {
        int s = src[i], d = dst[i];
        float cf = g_dinv[s] * w[i] * g_dinv[d];
        int p = atomicAdd(&g_cursor[d], 1);
        g_csr[p] = make_float2(cf, __int_as_float(s));
    }
}

// ---------------------------------------------------------------- XW = x @ [Wz|Wr|Wh]  (FFMA2)
__global__ void k_xw(const float* __restrict__ x,
                     const float* __restrict__ Wz,
                     const float* __restrict__ Wr,
                     const float* __restrict__ Wh, int n) {
    __shared__ float xs[64 * 32];
    __shared__ float ws[32 * 192];
    const int tid = threadIdx.x;
    const int row0 = blockIdx.x * 64;
    const int tx = tid & 15, ty = tid >> 4;

    u64 acc2[4][6];
#pragma unroll
    for (int r = 0; r < 4; r++)
#pragma unroll
        for (int c = 0; c < 6; c++) acc2[r][c] = 0ull;

    for (int k0 = 0; k0 < F_IN; k0 += 32) {
        for (int i = tid; i < 2048; i += 256) {
            int r = i >> 5, kk = i & 31;
            int row = row0 + r;
            xs[r * 32 + kk] = (row < n) ? x[(size_t)row * F_IN + k0 + kk] : 0.0f;
        }
        for (int i = tid; i < 6144; i += 256) {
            int kk = i / 192, j = i - kk * 192;
            const float* W = (j < 64) ? Wz : ((j < 128) ? Wr : Wh);
            int jj = j & 63;
            ws[kk * 192 + j] = W[(k0 + kk) * 64 + jj];
        }
        __syncthreads();

#pragma unroll 8
        for (int kk = 0; kk < 32; kk++) {
            u64 b2[6];
            {
                ulonglong2 t0 = *(const ulonglong2*)&ws[kk * 192 + tx * 12];
                ulonglong2 t1 = *(const ulonglong2*)&ws[kk * 192 + tx * 12 + 4];
                ulonglong2 t2 = *(const ulonglong2*)&ws[kk * 192 + tx * 12 + 8];
                b2[0] = t0.x; b2[1] = t0.y;
                b2[2] = t1.x; b2[3] = t1.y;
                b2[4] = t2.x; b2[5] = t2.y;
            }
#pragma unroll
            for (int r = 0; r < 4; r++) {
                float a = xs[(ty * 4 + r) * 32 + kk];
                u64 a2; PACK2(a2, a, a);
#pragma unroll
                for (int c = 0; c < 6; c++) FFMA2(acc2[r][c], a2, b2[c], acc2[r][c]);
            }
        }
        __syncthreads();
    }

#pragma unroll
    for (int r = 0; r < 4; r++) {
        int row = row0 + ty * 4 + r;
        if (row < n) {
            u64* dp = (u64*)&g_xw[(size_t)row * C3 + tx * 12];
#pragma unroll
            for (int c = 0; c < 6; c++) dp[c] = acc2[r][c];
        }
    }
}

// ---------------------------------------------------------------- CSR gather (no atomics, 4x unroll)
__global__ void k_gather(int n) {
    int warp = (blockIdx.x * blockDim.x + threadIdx.x) >> 5;
    if (warp >= n) return;
    const int lane = threadIdx.x & 31;

    const int r0 = g_rowptr[warp];
    const int r1 = g_rowptr[warp + 1];

    const float di = g_dinv[warp];
    const float sl = di * di;
    const float* __restrict__ xr = &g_xw[(size_t)warp * C3];

    float acc[6];
#pragma unroll
    for (int t = 0; t < 6; t++) acc[t] = sl * xr[lane + 32 * t];

    int p = r0;
    for (; p + 3 < r1; p += 4) {
        float2 e0 = g_csr[p];
        float2 e1 = g_csr[p + 1];
        float2 e2 = g_csr[p + 2];
        float2 e3 = g_csr[p + 3];
        const float* __restrict__ x0 = &g_xw[(size_t)__float_as_int(e0.y) * C3];
        const float* __restrict__ x1 = &g_xw[(size_t)__float_as_int(e1.y) * C3];
        const float* __restrict__ x2 = &g_xw[(size_t)__float_as_int(e2.y) * C3];
        const float* __restrict__ x3 = &g_xw[(size_t)__float_as_int(e3.y) * C3];
#pragma unroll
        for (int t = 0; t < 6; t++) {
            int j = lane + 32 * t;
            acc[t] += e0.x * x0[j] + e1.x * x1[j] + e2.x * x2[j] + e3.x * x3[j];
        }
    }
    for (; p < r1; p++) {
        float2 e0 = g_csr[p];
        const float* __restrict__ x0 = &g_xw[(size_t)__float_as_int(e0.y) * C3];
#pragma unroll
        for (int t = 0; t < 6; t++) acc[t] += e0.x * x0[lane + 32 * t];
    }

    float* __restrict__ ar = &g_agg[(size_t)warp * C3];
#pragma unroll
    for (int t = 0; t < 6; t++) ar[lane + 32 * t] = acc[t];
}

// ---------------------------------------------------------------- fused gates + GRU + output (FFMA2)
__global__ __launch_bounds__(512, 1)
void k_gates(const float* __restrict__ H,
             const float* __restrict__ bz, const float* __restrict__ br,
             const float* __restrict__ bh,
             const float* __restrict__ Lz, const float* __restrict__ lbz,
             const float* __restrict__ Lr, const float* __restrict__ lbr,
             const float* __restrict__ Lh, const float* __restrict__ lbh,
             const float* __restrict__ Wo, const float* __restrict__ bo,
             float* __restrict__ out, int n) {
    extern __shared__ float sm[];
    float* sH  = sm;            // 128*64
    float* sHR = sm + 8192;     // 128*64
    float* sL  = sm + 16384;    // 2 * 128*64
    float* sA  = sm + 32768;    // 2 * 128*64

    const int tid = threadIdx.x;
    const int node0 = blockIdx.x * 128;

    for (int i = tid; i < 8192; i += 512) {
        int r = i >> 6;
        int node = node0 + r;
        sH[i] = (node < n) ? H[(size_t)node * OUT + (i & 63)] : 0.0f;
    }
    for (int i = tid; i < 8192; i += 512) {
        sL[i] = Lz[i];
        sL[8192 + i] = Lr[i];
    }
    for (int i = tid; i < 8192; i += 512) {
        int r = i >> 6, j = i & 63;
        int node = node0 + r;
        if (node < n) {
            const float* ag = &g_agg[(size_t)node * C3];
            sA[i]        = ag[j]      + bz[j];
            sA[8192 + i] = ag[64 + j] + br[j];
        } else {
            sA[i] = 0.0f; sA[8192 + i] = 0.0f;
        }
    }
    __syncthreads();

    const int tx = tid & 15, ty = tid >> 4;
    const int r0 = ty * 4, c0 = tx * 4;

    u64 zacc2[4][2], racc2[4][2];
#pragma unroll
    for (int cp = 0; cp < 2; cp++) {
        u64 vz, vr;
        PACK2(vz, lbz[c0 + 2 * cp], lbz[c0 + 2 * cp + 1]);
        PACK2(vr, lbr[c0 + 2 * cp], lbr[c0 + 2 * cp + 1]);
#pragma unroll
        for (int rr = 0; rr < 4; rr++) { zacc2[rr][cp] = vz; racc2[rr][cp] = vr; }
    }

#pragma unroll 4
    for (int k = 0; k < 64; k++) {
        ulonglong2 z1 = *(const ulonglong2*)&sL[k * 64 + c0];
        ulonglong2 z2 = *(const ulonglong2*)&sL[(64 + k) * 64 + c0];
        ulonglong2 q1 = *(const ulonglong2*)&sL[8192 + k * 64 + c0];
        ulonglong2 q2 = *(const ulonglong2*)&sL[8192 + (64 + k) * 64 + c0];
#pragma unroll
        for (int rr = 0; rr < 4; rr++) {
            float az = sA[(r0 + rr) * 64 + k];
            float ar = sA[8192 + (r0 + rr) * 64 + k];
            float h  = sH[(r0 + rr) * 64 + k];
            u64 az2, ar2, h2;
            PACK2(az2, az, az); PACK2(ar2, ar, ar); PACK2(h2, h, h);
            FFMA2(zacc2[rr][0], az2, z1.x, zacc2[rr][0]);
            FFMA2(zacc2[rr][0], h2,  z2.x, zacc2[rr][0]);
            FFMA2(zacc2[rr][1], az2, z1.y, zacc2[rr][1]);
            FFMA2(zacc2[rr][1], h2,  z2.y, zacc2[rr][1]);
            FFMA2(racc2[rr][0], ar2, q1.x, racc2[rr][0]);
            FFMA2(racc2[rr][0], h2,  q2.x, racc2[rr][0]);
            FFMA2(racc2[rr][1], ar2, q1.y, racc2[rr][1]);
            FFMA2(racc2[rr][1], h2,  q2.y, racc2[rr][1]);
        }
    }

    float zacc[4][4];
#pragma unroll
    for (int rr = 0; rr < 4; rr++)
#pragma unroll
        for (int cp = 0; cp < 2; cp++) {
            float z0, z1f, w0, w1f;
            UNPACK2(z0, z1f, zacc2[rr][cp]);
            UNPACK2(w0, w1f, racc2[rr][cp]);
            float za = 1.0f / (1.0f + expf(-z0));
            float zb = 1.0f / (1.0f + expf(-z1f));
            float ra = 1.0f / (1.0f + expf(-w0));
            float rb = 1.0f / (1.0f + expf(-w1f));
            zacc[rr][2 * cp] = za; zacc[rr][2 * cp + 1] = zb;
            int idx = (r0 + rr) * 64 + c0 + 2 * cp;
            sHR[idx]     = ra * sH[idx];
            sHR[idx + 1] = rb * sH[idx + 1];
        }
    __syncthreads();

    // phase 2 overlays
    for (int i = tid; i < 8192; i += 512) sL[i] = Lh[i];
    for (int i = tid; i < 8192; i += 512) {
        int r = i >> 6, j = i & 63;
        int node = node0 + r;
        sA[i] = (node < n) ? g_agg[(size_t)node * C3 + 128 + j] + bh[j] : 0.0f;
    }
    __syncthreads();

    u64 hacc2[4][2];
#pragma unroll
    for (int cp = 0; cp < 2; cp++) {
        u64 vh;
        PACK2(vh, lbh[c0 + 2 * cp], lbh[c0 + 2 * cp + 1]);
#pragma unroll
        for (int rr = 0; rr < 4; rr++) hacc2[rr][cp] = vh;
    }

#pragma unroll 4
    for (int k = 0; k < 64; k++) {
        ulonglong2 h1 = *(const ulonglong2*)&sL[k * 64 + c0];
        ulonglong2 h2v = *(const ulonglong2*)&sL[(64 + k) * 64 + c0];
#pragma unroll
        for (int rr = 0; rr < 4; rr++) {
            float ah = sA[(r0 + rr) * 64 + k];
            float hr = sHR[(r0 + rr) * 64 + k];
            u64 ah2, hr2;
            PACK2(ah2, ah, ah); PACK2(hr2, hr, hr);
            FFMA2(hacc2[rr][0], ah2, h1.x,  hacc2[rr][0]);
            FFMA2(hacc2[rr][0], hr2, h2v.x, hacc2[rr][0]);
            FFMA2(hacc2[rr][1], ah2, h1.y,  hacc2[rr][1]);
            FFMA2(hacc2[rr][1], hr2, h2v.y, hacc2[rr][1]);
        }
    }

    float wov[4];
#pragma unroll
    for (int cc = 0; cc < 4; cc++) wov[cc] = Wo[c0 + cc];
    float yp[4] = {0.f, 0.f, 0.f, 0.f};

#pragma unroll
    for (int rr = 0; rr < 4; rr++) {
        int node = node0 + r0 + rr;
        float hv[4];
        UNPACK2(hv[0], hv[1], hacc2[rr][0]);
        UNPACK2(hv[2], hv[3], hacc2[rr][1]);
#pragma unroll
        for (int cc = 0; cc < 4; cc++) {
            float ht = tanhf(hv[cc]);
            float z = zacc[rr][cc];
            float h = sH[(r0 + rr) * 64 + c0 + cc];
            float hn = z * h + (1.0f - z) * ht;
            if (node < n) out[(size_t)n + (size_t)node * OUT + c0 + cc] = hn;
            yp[rr] += fmaxf(hn, 0.0f) * wov[cc];
        }
    }
#pragma unroll
    for (int off = 8; off > 0; off >>= 1)
#pragma unroll
        for (int rr = 0; rr < 4; rr++)
            yp[rr] += __shfl_xor_sync(0xffffffffu, yp[rr], off);
    if (tx == 0) {
        float b0 = bo[0];
#pragma unroll
        for (int rr = 0; rr < 4; rr++) {
            int node = node0 + r0 + rr;
            if (node < n) out[node] = yp[rr] + b0;
        }
    }
}

// ---------------------------------------------------------------- launch
extern "C" void kernel_launch(void* const* d_in, const int* in_sizes, int n_in,
                              void* d_out, int out_size) {
    const float* x   = (const float*)d_in[0];
    const int*   ei  = (const int*)d_in[1];
    const float* ew  = (const float*)d_in[2];
    const float* H   = (const float*)d_in[3];
    const float* Wz  = (const float*)d_in[5];
    const float* bz  = (const float*)d_in[6];
    const float* Wr  = (const float*)d_in[7];
    const float* br  = (const float*)d_in[8];
    const float* Wh  = (const float*)d_in[9];
    const float* bh  = (const float*)d_in[10];
    const float* Lz  = (const float*)d_in[11];
    const float* lbz = (const float*)d_in[12];
    const float* Lr  = (const float*)d_in[13];
    const float* lbr = (const float*)d_in[14];
    const float* Lh  = (const float*)d_in[15];
    const float* lbh = (const float*)d_in[16];
    const float* Wo  = (const float*)d_in[17];
    const float* bo  = (const float*)d_in[18];
    float* out = (float*)d_out;

    int n = in_sizes[0] / F_IN;
    int e = in_sizes[2];
    const int* src = ei;
    const int* dst = ei + e;
    int nblk = (n + 1023) / 1024;

    k_deg_init <<<(n + 255) / 256, 256>>>(n);
    k_deg_edges<<<(e + 255) / 256, 256>>>(dst, ew, e);
    k_rsqrt    <<<(n + 255) / 256, 256>>>(n);
    k_scan_a   <<<nblk, 1024>>>(n);
    k_scan_b   <<<1, 64>>>(n, nblk);
    k_scan_c   <<<(n + 255) / 256, 256>>>(n);
    k_fill     <<<(e + 255) / 256, 256>>>(src, dst, ew, e);
    k_xw       <<<(n + 63) / 64, 256>>>(x, Wz, Wr, Wh, n);
    k_gather   <<<(n * 32 + 255) / 256, 256>>>(n);

    cudaFuncSetAttribute(k_gates, cudaFuncAttributeMaxDynamicSharedMemorySize, 196608);
    k_gates<<<(n + 127) / 128, 512, 196608>>>(H, bz, br, bh, Lz, lbz, Lr, lbr,
                                              Lh, lbh, Wo, bo, out, n);
}

// round 8
// speedup vs baseline: 1.8751x; 1.1969x over previous
#include <cuda_runtime.h>
#include <cuda_bf16.h>
#include <math.h>
#include <cstdint>

#define F_IN 128
#define C3   192   // 3 * OUT
#define OUT  64
#define NMAX 50048
#define EMAX 800000

typedef unsigned long long u64;

// packed f32x2 FMA (Blackwell FFMA2 — only reachable via PTX)
#define FFMA2(d, a, b, c) \
    asm("fma.rn.f32x2 %0, %1, %2, %3;" : "=l"(d) : "l"(a), "l"(b), "l"(c))
#define PACK2(d, lo, hi) \
    asm("mov.b64 %0, {%1, %2};" : "=l"(d) : "f"(lo), "f"(hi))
#define UNPACK2(lo, hi, s) \
    asm("mov.b64 {%0, %1}, %2;" : "=f"(lo), "=f"(hi) : "l"(s))

// bf16 mma.sync (sm_80+ PTX, works on .target sm_100)
#define MMA16816(c, a0, a1, a2, a3, b0, b1)                                  \
    asm volatile("mma.sync.aligned.m16n8k16.row.col.f32.bf16.bf16.f32 "      \
        "{%0,%1,%2,%3}, {%4,%5,%6,%7}, {%8,%9}, {%0,%1,%2,%3};"              \
        : "+f"((c)[0]), "+f"((c)[1]), "+f"((c)[2]), "+f"((c)[3])             \
        : "r"(a0), "r"(a1), "r"(a2), "r"(a3), "r"(b0), "r"(b1))

__device__ float  g_dinv[NMAX];
__device__ float  g_xw [(size_t)NMAX * C3];
__device__ float  g_agg[(size_t)NMAX * C3];
__device__ int    g_cnt[NMAX];
__device__ int    g_rowptr[NMAX + 1];
__device__ int    g_cursor[NMAX];
__device__ int    g_bsum[64];
__device__ int    g_boff[64];
__device__ float2 g_csr[EMAX];
// prepacked bf16 weight split images, B = W^T, plain [nn][k] row-major 192x128
__device__ __align__(16) __nv_bfloat16 g_bhi[C3 * F_IN];
__device__ __align__(16) __nv_bfloat16 g_blo[C3 * F_IN];

// ---------------------------------------------------------------- degree/norm + in-degree hist
__global__ void k_deg_init(int n) {
    int i = blockIdx.x * blockDim.x + threadIdx.x;
    if (i < n) { g_dinv[i] = 1.0f; g_cnt[i] = 0; }
}

__global__ void k_deg_edges(const int* __restrict__ dst,
                            const float* __restrict__ w, int e) {
    int i = blockIdx.x * blockDim.x + threadIdx.x;
    if (i < e) {
        int d = dst[i];
        atomicAdd(&g_dinv[d], w[i]);
        atomicAdd(&g_cnt[d], 1);
    }
}

__global__ void k_rsqrt(int n) {
    int i = blockIdx.x * blockDim.x + threadIdx.x;
    if (i < n) {
        float d = g_dinv[i];
        g_dinv[i] = (d > 0.0f) ? rsqrtf(d) : 0.0f;
    }
}

// ---------------------------------------------------------------- coalesced hierarchical scan
__global__ void k_scan_a(int n) {
    __shared__ int s[1024];
    int tid = threadIdx.x;
    int i = blockIdx.x * 1024 + tid;
    int v = (i < n) ? g_cnt[i] : 0;
    s[tid] = v;
    __syncthreads();
    for (int d = 1; d < 1024; d <<= 1) {
        int t = (tid >= d) ? s[tid - d] : 0;
        __syncthreads();
        s[tid] += t;
        __syncthreads();
    }
    if (i < n) g_rowptr[i] = s[tid] - v;
    if (tid == 1023) g_bsum[blockIdx.x] = s[1023];
}

__global__ void k_scan_b(int n, int nblk) {
    __shared__ int s[64];
    int tid = threadIdx.x;
    int v = (tid < nblk) ? g_bsum[tid] : 0;
    s[tid] = v;
    __syncthreads();
    for (int d = 1; d < 64; d <<= 1) {
        int t = (tid >= d) ? s[tid - d] : 0;
        __syncthreads();
        s[tid] += t;
        __syncthreads();
    }
    if (tid < nblk) g_boff[tid] = s[tid] - v;
    if (tid == 63) g_rowptr[n] = s[63];
}

__global__ void k_scan_c(int n) {
    int i = blockIdx.x * blockDim.x + threadIdx.x;
    if (i < n) {
        int v = g_rowptr[i] + g_boff[i >> 10];
        g_rowptr[i] = v;
        g_cursor[i] = v;
    }
}

// ---------------------------------------------------------------- bin edges by dst
__global__ void k_fill(const int* __restrict__ src, const int* __restrict__ dst,
                       const float* __restrict__ w, int e) {
    int i = blockIdx.x * blockDim.x + threadIdx.x;
    if (i < e) {
        int s = src[i], d = dst[i];
        float cf = g_dinv[s] * w[i] * g_dinv[d];
        int p = atomicAdd(&g_cursor[d], 1);
        g_csr[p] = make_float2(cf, __int_as_float(s));
    }
}

// ---------------------------------------------------------------- weight split/transpose
// B[nn][k] = W[k][nn&63] for the right gate; bf16 hi/lo split.
__global__ void k_wsplit(const float* __restrict__ Wz, const float* __restrict__ Wr,
                         const float* __restrict__ Wh) {
    int i = blockIdx.x * blockDim.x + threadIdx.x;
    if (i >= C3 * F_IN) return;
    int nn = i >> 7, k = i & 127;
    const float* W = (nn < 64) ? Wz : ((nn < 128) ? Wr : Wh);
    float v = W[k * 64 + (nn & 63)];
    __nv_bfloat16 hi = __float2bfloat16(v);
    __nv_bfloat16 lo = __float2bfloat16(v - __bfloat162float(hi));
    g_bhi[i] = hi;
    g_blo[i] = lo;
}

// ---------------------------------------------------------------- mma.sync GEMM: g_xw = x @ [Wz|Wr|Wh]
// 3-term bf16 split: Ahi*Bhi + Ahi*Blo + Alo*Bhi, fp32 accumulate.
// Block: 128 rows x 64-col group (blockIdx.y). 8 warps, warp w -> rows [16w,16w+16).
// smem padded stride 136 bf16 -> fragment LDS provably bank-conflict-free.
#define XPAD 136
__global__ __launch_bounds__(256, 1)
void k_xw_mma(const float* __restrict__ x, int n) {
    extern __shared__ __align__(16) __nv_bfloat16 sb[];
    __nv_bfloat16* sAhi = sb;                  // 128 x 136
    __nv_bfloat16* sAlo = sb + 128 * XPAD;     // 128 x 136
    __nv_bfloat16* sBhi = sb + 256 * XPAD;     // 64 x 136
    __nv_bfloat16* sBlo = sb + 320 * XPAD;     // 64 x 136

    const int tid = threadIdx.x;
    const int row0 = blockIdx.x * 128;
    const int g = blockIdx.y;                  // col group: 64 cols

    // fill A (coalesced float4 reads, split to hi/lo)
    for (int i = tid; i < 4096; i += 256) {
        int r = i >> 5;
        int c = (i & 31) * 4;
        float4 v = make_float4(0.f, 0.f, 0.f, 0.f);
        if (row0 + r < n) v = *(const float4*)&x[(size_t)(row0 + r) * F_IN + c];
        __nv_bfloat16 h0 = __float2bfloat16(v.x), h1 = __float2bfloat16(v.y);
        __nv_bfloat16 h2 = __float2bfloat16(v.z), h3 = __float2bfloat16(v.w);
        __nv_bfloat16 l0 = __float2bfloat16(v.x - __bfloat162float(h0));
        __nv_bfloat16 l1 = __float2bfloat16(v.y - __bfloat162float(h1));
        __nv_bfloat16 l2 = __float2bfloat16(v.z - __bfloat162float(h2));
        __nv_bfloat16 l3 = __float2bfloat16(v.w - __bfloat162float(h3));
        int o = r * XPAD + c;
        *(__nv_bfloat162*)&sAhi[o]     = __nv_bfloat162(h0, h1);
        *(__nv_bfloat162*)&sAhi[o + 2] = __nv_bfloat162(h2, h3);
        *(__nv_bfloat162*)&sAlo[o]     = __nv_bfloat162(l0, l1);
        *(__nv_bfloat162*)&sAlo[o + 2] = __nv_bfloat162(l2, l3);
    }
    // fill B group (float4 = 8 bf16 per copy)
    for (int i = tid; i < 1024; i += 256) {
        int r = i >> 4;
        int c = (i & 15) * 8;
        *(float4*)&sBhi[r * XPAD + c] = *(const float4*)&g_bhi[(size_t)(g * 64 + r) * F_IN + c];
        *(float4*)&sBlo[r * XPAD + c] = *(const float4*)&g_blo[(size_t)(g * 64 + r) * F_IN + c];
    }
    __syncthreads();

    const int wid = tid >> 5, lane = tid & 31;
    const int gid = lane >> 2, tig = lane & 3;
    const int arow = wid * 16 + gid;

    float acc[8][4];
#pragma unroll
    for (int c = 0; c < 8; c++)
#pragma unroll
        for (int q = 0; q < 4; q++) acc[c][q] = 0.0f;

#pragma unroll
    for (int ks = 0; ks < 8; ks++) {
        const int k0 = ks * 16;
        const __nv_bfloat16* pa = &sAhi[arow * XPAD + k0 + tig * 2];
        const __nv_bfloat16* pl = &sAlo[arow * XPAD + k0 + tig * 2];
        uint32_t ah0 = *(const uint32_t*)pa;
        uint32_t ah1 = *(const uint32_t*)(pa + 8 * XPAD);
        uint32_t ah2 = *(const uint32_t*)(pa + 8);
        uint32_t ah3 = *(const uint32_t*)(pa + 8 * XPAD + 8);
        uint32_t al0 = *(const uint32_t*)pl;
        uint32_t al1 = *(const uint32_t*)(pl + 8 * XPAD);
        uint32_t al2 = *(const uint32_t*)(pl + 8);
        uint32_t al3 = *(const uint32_t*)(pl + 8 * XPAD + 8);
#pragma unroll
        for (int c = 0; c < 8; c++) {
            const __nv_bfloat16* pb = &sBhi[(c * 8 + gid) * XPAD + k0 + tig * 2];
            const __nv_bfloat16* pq = &sBlo[(c * 8 + gid) * XPAD + k0 + tig * 2];
            uint32_t bh0 = *(const uint32_t*)pb;
            uint32_t bh1 = *(const uint32_t*)(pb + 8);
            uint32_t bl0 = *(const uint32_t*)pq;
            uint32_t bl1 = *(const uint32_t*)(pq + 8);
            MMA16816(acc[c], ah0, ah1, ah2, ah3, bh0, bh1);
            MMA16816(acc[c], ah0, ah1, ah2, ah3, bl0, bl1);
            MMA16816(acc[c], al0, al1, al2, al3, bh0, bh1);
        }
    }

    // epilogue: c0/c1 = (row, col), (row, col+1); c2/c3 = row+8
    const int gr = row0 + arow;
#pragma unroll
    for (int c = 0; c < 8; c++) {
        int col = g * 64 + c * 8 + tig * 2;
        if (gr < n)
            *(float2*)&g_xw[(size_t)gr * C3 + col] = make_float2(acc[c][0], acc[c][1]);
        if (gr + 8 < n)
            *(float2*)&g_xw[(size_t)(gr + 8) * C3 + col] = make_float2(acc[c][2], acc[c][3]);
    }
}

// ---------------------------------------------------------------- CSR gather (no atomics, 4x unroll)
__global__ void k_gather(int n) {
    int warp = (blockIdx.x * blockDim.x + threadIdx.x) >> 5;
    if (warp >= n) return;
    const int lane = threadIdx.x & 31;

    const int r0 = g_rowptr[warp];
    const int r1 = g_rowptr[warp + 1];

    const float di = g_dinv[warp];
    const float sl = di * di;
    const float* __restrict__ xr = &g_xw[(size_t)warp * C3];

    float acc[6];
#pragma unroll
    for (int t = 0; t < 6; t++) acc[t] = sl * xr[lane + 32 * t];

    int p = r0;
    for (; p + 3 < r1; p += 4) {
        float2 e0 = g_csr[p];
        float2 e1 = g_csr[p + 1];
        float2 e2 = g_csr[p + 2];
        float2 e3 = g_csr[p + 3];
        const float* __restrict__ x0 = &g_xw[(size_t)__float_as_int(e0.y) * C3];
        const float* __restrict__ x1 = &g_xw[(size_t)__float_as_int(e1.y) * C3];
        const float* __restrict__ x2 = &g_xw[(size_t)__float_as_int(e2.y) * C3];
        const float* __restrict__ x3 = &g_xw[(size_t)__float_as_int(e3.y) * C3];
#pragma unroll
        for (int t = 0; t < 6; t++) {
            int j = lane + 32 * t;
            acc[t] += e0.x * x0[j] + e1.x * x1[j] + e2.x * x2[j] + e3.x * x3[j];
        }
    }
    for (; p < r1; p++) {
        float2 e0 = g_csr[p];
        const float* __restrict__ x0 = &g_xw[(size_t)__float_as_int(e0.y) * C3];
#pragma unroll
        for (int t = 0; t < 6; t++) acc[t] += e0.x * x0[lane + 32 * t];
    }

    float* __restrict__ ar = &g_agg[(size_t)warp * C3];
#pragma unroll
    for (int t = 0; t < 6; t++) ar[lane + 32 * t] = acc[t];
}

// ---------------------------------------------------------------- fused gates + GRU + output (FFMA2)
__global__ __launch_bounds__(512, 1)
void k_gates(const float* __restrict__ H,
             const float* __restrict__ bz, const float* __restrict__ br,
             const float* __restrict__ bh,
             const float* __restrict__ Lz, const float* __restrict__ lbz,
             const float* __restrict__ Lr, const float* __restrict__ lbr,
             const float* __restrict__ Lh, const float* __restrict__ lbh,
             const float* __restrict__ Wo, const float* __restrict__ bo,
             float* __restrict__ out, int n) {
    extern __shared__ float sm[];
    float* sH  = sm;            // 128*64
    float* sHR = sm + 8192;     // 128*64
    float* sL  = sm + 16384;    // 2 * 128*64
    float* sA  = sm + 32768;    // 2 * 128*64

    const int tid = threadIdx.x;
    const int node0 = blockIdx.x * 128;

    for (int i = tid; i < 8192; i += 512) {
        int r = i >> 6;
        int node = node0 + r;
        sH[i] = (node < n) ? H[(size_t)node * OUT + (i & 63)] : 0.0f;
    }
    for (int i = tid; i < 8192; i += 512) {
        sL[i] = Lz[i];
        sL[8192 + i] = Lr[i];
    }
    for (int i = tid; i < 8192; i += 512) {
        int r = i >> 6, j = i & 63;
        int node = node0 + r;
        if (node < n) {
            const float* ag = &g_agg[(size_t)node * C3];
            sA[i]        = ag[j]      + bz[j];
            sA[8192 + i] = ag[64 + j] + br[j];
        } else {
            sA[i] = 0.0f; sA[8192 + i] = 0.0f;
        }
    }
    __syncthreads();

    const int tx = tid & 15, ty = tid >> 4;
    const int r0 = ty * 4, c0 = tx * 4;

    u64 zacc2[4][2], racc2[4][2];
#pragma unroll
    for (int cp = 0; cp < 2; cp++) {
        u64 vz, vr;
        PACK2(vz, lbz[c0 + 2 * cp], lbz[c0 + 2 * cp + 1]);
        PACK2(vr, lbr[c0 + 2 * cp], lbr[c0 + 2 * cp + 1]);
#pragma unroll
        for (int rr = 0; rr < 4; rr++) { zacc2[rr][cp] = vz; racc2[rr][cp] = vr; }
    }

#pragma unroll 4
    for (int k = 0; k < 64; k++) {
        ulonglong2 z1 = *(const ulonglong2*)&sL[k * 64 + c0];
        ulonglong2 z2 = *(const ulonglong2*)&sL[(64 + k) * 64 + c0];
        ulonglong2 q1 = *(const ulonglong2*)&sL[8192 + k * 64 + c0];
        ulonglong2 q2 = *(const ulonglong2*)&sL[8192 + (64 + k) * 64 + c0];
#pragma unroll
        for (int rr = 0; rr < 4; rr++) {
            float az = sA[(r0 + rr) * 64 + k];
            float ar = sA[8192 + (r0 + rr) * 64 + k];
            float h  = sH[(r0 + rr) * 64 + k];
            u64 az2, ar2, h2;
            PACK2(az2, az, az); PACK2(ar2, ar, ar); PACK2(h2, h, h);
            FFMA2(zacc2[rr][0], az2, z1.x, zacc2[rr][0]);
            FFMA2(zacc2[rr][0], h2,  z2.x, zacc2[rr][0]);
            FFMA2(zacc2[rr][1], az2, z1.y, zacc2[rr][1]);
            FFMA2(zacc2[rr][1], h2,  z2.y, zacc2[rr][1]);
            FFMA2(racc2[rr][0], ar2, q1.x, racc2[rr][0]);
            FFMA2(racc2[rr][0], h2,  q2.x, racc2[rr][0]);
            FFMA2(racc2[rr][1], ar2, q1.y, racc2[rr][1]);
            FFMA2(racc2[rr][1], h2,  q2.y, racc2[rr][1]);
        }
    }

    float zacc[4][4];
#pragma unroll
    for (int rr = 0; rr < 4; rr++)
#pragma unroll
        for (int cp = 0; cp < 2; cp++) {
            float z0, z1f, w0, w1f;
            UNPACK2(z0, z1f, zacc2[rr][cp]);
            UNPACK2(w0, w1f, racc2[rr][cp]);
            float za = 1.0f / (1.0f + expf(-z0));
            float zb = 1.0f / (1.0f + expf(-z1f));
            float ra = 1.0f / (1.0f + expf(-w0));
            float rb = 1.0f / (1.0f + expf(-w1f));
            zacc[rr][2 * cp] = za; zacc[rr][2 * cp + 1] = zb;
            int idx = (r0 + rr) * 64 + c0 + 2 * cp;
            sHR[idx]     = ra * sH[idx];
            sHR[idx + 1] = rb * sH[idx + 1];
        }
    __syncthreads();

    for (int i = tid; i < 8192; i += 512) sL[i] = Lh[i];
    for (int i = tid; i < 8192; i += 512) {
        int r = i >> 6, j = i & 63;
        int node = node0 + r;
        sA[i] = (node < n) ? g_agg[(size_t)node * C3 + 128 + j] + bh[j] : 0.0f;
    }
    __syncthreads();

    u64 hacc2[4][2];
#pragma unroll
    for (int cp = 0; cp < 2; cp++) {
        u64 vh;
        PACK2(vh, lbh[c0 + 2 * cp], lbh[c0 + 2 * cp + 1]);
#pragma unroll
        for (int rr = 0; rr < 4; rr++) hacc2[rr][cp] = vh;
    }

#pragma unroll 4
    for (int k = 0; k < 64; k++) {
        ulonglong2 h1 = *(const ulonglong2*)&sL[k * 64 + c0];
        ulonglong2 h2v = *(const ulonglong2*)&sL[(64 + k) * 64 + c0];
#pragma unroll
        for (int rr = 0; rr < 4; rr++) {
            float ah = sA[(r0 + rr) * 64 + k];
            float hr = sHR[(r0 + rr) * 64 + k];
            u64 ah2, hr2;
            PACK2(ah2, ah, ah); PACK2(hr2, hr, hr);
            FFMA2(hacc2[rr][0], ah2, h1.x,  hacc2[rr][0]);
            FFMA2(hacc2[rr][0], hr2, h2v.x, hacc2[rr][0]);
            FFMA2(hacc2[rr][1], ah2, h1.y,  hacc2[rr][1]);
            FFMA2(hacc2[rr][1], hr2, h2v.y, hacc2[rr][1]);
        }
    }

    float wov[4];
#pragma unroll
    for (int cc = 0; cc < 4; cc++) wov[cc] = Wo[c0 + cc];
    float yp[4] = {0.f, 0.f, 0.f, 0.f};

#pragma unroll
    for (int rr = 0; rr < 4; rr++) {
        int node = node0 + r0 + rr;
        float hv[4];
        UNPACK2(hv[0], hv[1], hacc2[rr][0]);
        UNPACK2(hv[2], hv[3], hacc2[rr][1]);
#pragma unroll
        for (int cc = 0; cc < 4; cc++) {
            float ht = tanhf(hv[cc]);
            float z = zacc[rr][cc];
            float h = sH[(r0 + rr) * 64 + c0 + cc];
            float hn = z * h + (1.0f - z) * ht;
            if (node < n) out[(size_t)n + (size_t)node * OUT + c0 + cc] = hn;
            yp[rr] += fmaxf(hn, 0.0f) * wov[cc];
        }
    }
#pragma unroll
    for (int off = 8; off > 0; off >>= 1)
#pragma unroll
        for (int rr = 0; rr < 4; rr++)
            yp[rr] += __shfl_xor_sync(0xffffffffu, yp[rr], off);
    if (tx == 0) {
        float b0 = bo[0];
#pragma unroll
        for (int rr = 0; rr < 4; rr++) {
            int node = node0 + r0 + rr;
            if (node < n) out[node] = yp[rr] + b0;
        }
    }
}

// ---------------------------------------------------------------- launch
extern "C" void kernel_launch(void* const* d_in, const int* in_sizes, int n_in,
                              void* d_out, int out_size) {
    const float* x   = (const float*)d_in[0];
    const int*   ei  = (const int*)d_in[1];
    const float* ew  = (const float*)d_in[2];
    const float* H   = (const float*)d_in[3];
    const float* Wz  = (const float*)d_in[5];
    const float* bz  = (const float*)d_in[6];
    const float* Wr  = (const float*)d_in[7];
    const float* br  = (const float*)d_in[8];
    const float* Wh  = (const float*)d_in[9];
    const float* bh  = (const float*)d_in[10];
    const float* Lz  = (const float*)d_in[11];
    const float* lbz = (const float*)d_in[12];
    const float* Lr  = (const float*)d_in[13];
    const float* lbr = (const float*)d_in[14];
    const float* Lh  = (const float*)d_in[15];
    const float* lbh = (const float*)d_in[16];
    const float* Wo  = (const float*)d_in[17];
    const float* bo  = (const float*)d_in[18];
    float* out = (float*)d_out;

    int n = in_sizes[0] / F_IN;
    int e = in_sizes[2];
    const int* src = ei;
    const int* dst = ei + e;
    int nblk = (n + 1023) / 1024;

    k_wsplit   <<<(C3 * F_IN + 255) / 256, 256>>>(Wz, Wr, Wh);
    k_deg_init <<<(n + 255) / 256, 256>>>(n);
    k_deg_edges<<<(e + 255) / 256, 256>>>(dst, ew, e);
    k_rsqrt    <<<(n + 255) / 256, 256>>>(n);
    k_scan_a   <<<nblk, 1024>>>(n);
    k_scan_b   <<<1, 64>>>(n, nblk);
    k_scan_c   <<<(n + 255) / 256, 256>>>(n);
    k_fill     <<<(e + 255) / 256, 256>>>(src, dst, ew, e);

    int xw_smem = 384 * XPAD * 2;   // 104448 B
    cudaFuncSetAttribute(k_xw_mma, cudaFuncAttributeMaxDynamicSharedMemorySize, xw_smem);
    dim3 xg((n + 127) / 128, 3);
    k_xw_mma   <<<xg, 256, xw_smem>>>(x, n);

    k_gather   <<<(n * 32 + 255) / 256, 256>>>(n);

    cudaFuncSetAttribute(k_gates, cudaFuncAttributeMaxDynamicSharedMemorySize, 196608);
    k_gates<<<(n + 127) / 128, 512, 196608>>>(H, bz, br, bh, Lz, lbz, Lr, lbr,
                                              Lh, lbh, Wo, bo, out, n);
}